// round 6
// baseline (speedup 1.0000x reference)
#include <cuda_runtime.h>
#include <cstdint>

// ---------------- problem sizes ----------------
#define B_SZ   8
#define C_IN   256
#define T_SZ   16000
#define C_OUT  512
#define TP     (T_SZ + 2)       // padded token rows (halo t=-1, t=T)
#define TILES_T 250             // 16000 / 64
#define N_TILES_TOTAL 2000      // 8 * 250
#define QMAX   37               // 148 / 4
#define TILE_ROWS 66            // 64 tokens + 2 halo rows
#define ROW_B  256              // bytes per xb row (256 int8 cin)
#define STAGE_B (TILE_ROWS * ROW_B)   // 16896
#define NCHUNK  1056            // 66 * 16 cp.async 16B chunks
#define INV_CNT (1.0f / 4096000.0f)

// ---------------- device scratch ----------------
__device__ __align__(16) signed char g_xb[(size_t)B_SZ * TP * C_IN];  // [b][t+1][cin] int8 +-1
__device__ __align__(16) signed char g_wA[C_OUT * 768];               // [co][tap*256+cin] int8 +-1
__device__ float g_alpha[C_OUT];
__device__ float g_beta_sum[B_SZ];

__device__ __forceinline__ uint32_t smem_u32(const void* p) {
    uint32_t a;
    asm("{ .reg .u64 t; cvta.to.shared.u64 t, %1; cvt.u32.u64 %0, t; }" : "=r"(a) : "l"(p));
    return a;
}

// ---------------- kernel 1: zero beta accumulators + halo rows ----------------
__global__ void prep_zero() {
    int tid = threadIdx.x;
    if (tid < B_SZ) g_beta_sum[tid] = 0.0f;
    for (int i = tid; i < B_SZ * C_IN; i += 256) {
        int b = i >> 8, c = i & 255;
        g_xb[((size_t)b * TP) * C_IN + c] = 0;
        g_xb[((size_t)b * TP + (TP - 1)) * C_IN + c] = 0;
    }
}

// ---------------- kernel 2: binarize + transpose x, accumulate |x| ----------------
// grid (250, 4, 8), block 256. Tile [64 cin][64 t] -> [64 t][64 cin] int8.
// smem layout: byte (t, ci) at t*64 + (ci ^ ((t>>4)<<4))  (16B-block XOR swizzle)
__global__ void prep_x(const float* __restrict__ x) {
    __shared__ signed char st[4096];
    __shared__ float red[8];
    int b = blockIdx.z, c0 = blockIdx.y * 64, t0 = blockIdx.x * 64;
    int tid = threadIdx.x;
    int ci = tid >> 2, tj0 = (tid & 3) * 16;
    int tq = tid & 3;                       // == t_local>>4 for all 16 elements
    int cisw = ci ^ (tq << 4);

    const float4* xp = (const float4*)(x + ((size_t)(b * C_IN + c0 + ci)) * T_SZ + t0 + tj0);
    float acc = 0.0f;
#pragma unroll
    for (int v = 0; v < 4; v++) {
        float4 f = xp[v];
        float vals[4] = {f.x, f.y, f.z, f.w};
#pragma unroll
        for (int e = 0; e < 4; e++) {
            float val = vals[e];
            acc += fabsf(val);
            st[(tj0 + 4 * v + e) * 64 + cisw] = (val >= 0.0f) ? (signed char)1 : (signed char)-1;
        }
    }
#pragma unroll
    for (int off = 16; off > 0; off >>= 1)
        acc += __shfl_xor_sync(0xFFFFFFFFu, acc, off);
    if ((tid & 31) == 0) red[tid >> 5] = acc;
    __syncthreads();
    if (tid == 0) {
        float s = 0.0f;
#pragma unroll
        for (int i = 0; i < 8; i++) s += red[i];
        atomicAdd(&g_beta_sum[b], s);
    }
    // read row tr, 16 cin chunk part*16 (aligned uint4, swizzle-consistent)
    int tr = tid >> 2, part = tid & 3;
    uint4 v = *(const uint4*)(st + tr * 64 + ((part * 16) ^ (((tr >> 4) & 3) << 4)));
    *(uint4*)(g_xb + ((size_t)b * TP + (t0 + tr + 1)) * C_IN + c0 + part * 16) = v;
}

// ---------------- kernel 3: alpha + packed sign weights ----------------
__global__ void prep_w(const float* __restrict__ w) {
    int co = blockIdx.x * 256 + threadIdx.x;
    if (co >= C_OUT) return;
    const float* wr = w + (size_t)co * 768;
    float s = 0.0f;
#pragma unroll 4
    for (int j = 0; j < 768; j++) s += fabsf(wr[j]);
    g_alpha[co] = s * (1.0f / 768.0f);
    signed char* wa = g_wA + (size_t)co * 768;
    for (int cin = 0; cin < C_IN; cin++) {
#pragma unroll
        for (int tap = 0; tap < 3; tap++)
            wa[tap * 256 + cin] = (wr[cin * 3 + tap] >= 0.0f) ? (signed char)1 : (signed char)-1;
    }
}

// ---------------- GEMM: persistent mma.sync int8 ----------------
// B smem: row r (= token t0-1+r), 256B; byte (r, col) at r*256 + (col ^ ((r&7)<<4))
__device__ __forceinline__ void issue_tile(uint32_t slot, int b, int t0, int tid) {
    const signed char* src = g_xb + ((size_t)b * TP + t0) * C_IN;
#pragma unroll
    for (int k = 0; k < 5; k++) {
        int idx = tid + k * 256;
        if (idx < NCHUNK) {
            int r = idx >> 4, c = idx & 15;
            uint32_t dst = slot + r * 256 + ((c * 16) ^ ((r & 7) << 4));
            asm volatile("cp.async.cg.shared.global [%0], [%1], 16;"
                         :: "r"(dst), "l"(src + r * 256 + c * 16) : "memory");
        }
    }
}

#define MMA_S8(D, A, B0, B1)                                                        \
    asm volatile("mma.sync.aligned.m16n8k32.row.col.s32.s8.s8.s32 "                  \
                 "{%0,%1,%2,%3}, {%4,%5,%6,%7}, {%8,%9}, {%0,%1,%2,%3};"             \
                 : "+r"(D[0]), "+r"(D[1]), "+r"(D[2]), "+r"(D[3])                    \
                 : "r"(A[0]), "r"(A[1]), "r"(A[2]), "r"(A[3]), "r"(B0), "r"(B1))

__global__ void __launch_bounds__(256, 1)
gemm_kernel(float* __restrict__ out) {
    __shared__ __align__(256) signed char smemB[2][STAGE_B];
    uint32_t sb0 = smem_u32(&smemB[0][0]);
    int tid = threadIdx.x, wid = tid >> 5, lane = tid & 31;
    int gID = lane >> 2, tig = lane & 3;
    int m = blockIdx.x & 3, q = blockIdx.x >> 2;
    int ntiles = (N_TILES_TOTAL - q + QMAX - 1) / QMAX;

    // ---- A fragments resident in registers (96 regs) ----
    int co0 = m * 128 + wid * 16 + gID;
    const uint32_t* wa0 = (const uint32_t*)(g_wA + (size_t)co0 * 768);
    const uint32_t* wa1 = (const uint32_t*)(g_wA + (size_t)(co0 + 8) * 768);
    uint32_t afr[24][4];
#pragma unroll
    for (int kc = 0; kc < 24; kc++) {
        afr[kc][0] = wa0[kc * 8 + tig];       // rows gID,   k = kc*32 + tig*4 .. +3
        afr[kc][1] = wa1[kc * 8 + tig];       // rows gID+8
        afr[kc][2] = wa0[kc * 8 + 4 + tig];   // k + 16
        afr[kc][3] = wa1[kc * 8 + 4 + tig];
    }
    float alpha0 = g_alpha[co0], alpha1 = g_alpha[co0 + 8];

    // ldmatrix per-thread address components: lane -> (matrix m_ld, row r_ld)
    int r_ld = lane & 7, m_ld = lane >> 3;
    int coffb = (m_ld >> 1) * 32 + (m_ld & 1) * 16;  // cin offset within 64-pair

    // ---- prologue: stage tiles 0,1 ----
    for (int s = 0; s < 2; s++) {
        if (s < ntiles) {
            int n = q + QMAX * s;
            int b = n / TILES_T, tl = n - b * TILES_T;
            issue_tile(sb0 + s * STAGE_B, b, tl * 64, tid);
        }
        asm volatile("cp.async.commit_group;" ::: "memory");
    }

    for (int j = 0; j < ntiles; j++) {
        int n = q + QMAX * j;
        int b = n / TILES_T, tl = n - b * TILES_T;
        asm volatile("cp.async.wait_group 1;" ::: "memory");
        __syncthreads();
        uint32_t stage = sb0 + (uint32_t)(j & 1) * STAGE_B;

        uint32_t base[3], swz[3];
#pragma unroll
        for (int tap = 0; tap < 3; tap++) {
            base[tap] = stage + (uint32_t)(r_ld + tap) * 256;
            swz[tap] = (uint32_t)((r_ld + tap) & 7) << 4;
        }

        int32_t acc[8][4];
#pragma unroll
        for (int nb = 0; nb < 8; nb++) {
            acc[nb][0] = 0; acc[nb][1] = 0; acc[nb][2] = 0; acc[nb][3] = 0;
        }

#pragma unroll
        for (int nb = 0; nb < 8; nb++) {
#pragma unroll
            for (int tap = 0; tap < 3; tap++) {
#pragma unroll
                for (int p = 0; p < 4; p++) {
                    uint32_t addr = base[tap] + (uint32_t)nb * 2048 +
                                    (((uint32_t)(p * 64 + coffb)) ^ swz[tap]);
                    uint32_t b0, b1, b2, b3;
                    asm volatile("ldmatrix.sync.aligned.m8n8.x4.shared.b16 {%0,%1,%2,%3}, [%4];"
                                 : "=r"(b0), "=r"(b1), "=r"(b2), "=r"(b3) : "r"(addr));
                    int kc = tap * 8 + p * 2;
                    MMA_S8(acc[nb], afr[kc], b0, b1);
                    MMA_S8(acc[nb], afr[kc + 1], b2, b3);
                }
            }
        }

        // ---- epilogue: scale + coalesced stores ----
        float sc = g_beta_sum[b] * INV_CNT;
        float s0 = alpha0 * sc, s1 = alpha1 * sc;
        float* ob = out + ((size_t)(b * C_OUT + co0)) * T_SZ + tl * 64 + tig * 2;
        float* ob8 = ob + (size_t)8 * T_SZ;
#pragma unroll
        for (int nb = 0; nb < 8; nb++) {
            float2 v0 = make_float2((float)acc[nb][0] * s0, (float)acc[nb][1] * s0);
            float2 v1 = make_float2((float)acc[nb][2] * s1, (float)acc[nb][3] * s1);
            *(float2*)(ob + nb * 8) = v0;
            *(float2*)(ob8 + nb * 8) = v1;
        }

        __syncthreads();   // slot fully consumed
        if (j + 2 < ntiles) {
            int n2 = q + QMAX * (j + 2);
            int b2 = n2 / TILES_T, tl2 = n2 - b2 * TILES_T;
            issue_tile(sb0 + (uint32_t)(j & 1) * STAGE_B, b2, tl2 * 64, tid);
        }
        asm volatile("cp.async.commit_group;" ::: "memory");
    }
}

// ---------------- host launcher ----------------
extern "C" void kernel_launch(void* const* d_in, const int* in_sizes, int n_in,
                              void* d_out, int out_size) {
    const float* x = (const float*)d_in[0];
    const float* w = (const float*)d_in[1];
    float* out = (float*)d_out;

    prep_zero<<<1, 256>>>();
    prep_x<<<dim3(TILES_T, 4, B_SZ), 256>>>(x);
    prep_w<<<2, 256>>>(w);
    gemm_kernel<<<148, 256>>>(out);
}

// round 7
// speedup vs baseline: 1.0036x; 1.0036x over previous
#include <cuda_runtime.h>
#include <cstdint>

// ---------------- problem sizes ----------------
#define B_SZ   8
#define C_IN   256
#define T_SZ   16000
#define C_OUT  512
#define TP     (T_SZ + 2)       // padded token rows (halo t=-1, t=T)
#define TILES_T 250             // 16000 / 64
#define N_TILES_TOTAL 2000      // 8 * 250
#define QMAX   37               // 148 / 4
#define TILE_ROWS 66            // 64 tokens + 2 halo rows
#define ROW_B  256              // bytes per xb row (256 int8 cin)
#define STAGE_B (TILE_ROWS * ROW_B)   // 16896
#define NCHUNK  1056            // 66 * 16 cp.async 16B chunks
#define INV_CNT (1.0f / 4096000.0f)

// ---------------- device scratch ----------------
__device__ __align__(16) signed char g_xb[(size_t)B_SZ * TP * C_IN];  // [b][t+1][cin] int8 +-1
__device__ __align__(16) signed char g_wA[C_OUT * 768];               // [co][tap*256+cin] int8 +-1
__device__ float g_alpha[C_OUT];
__device__ float g_beta_sum[B_SZ];

__device__ __forceinline__ uint32_t smem_u32(const void* p) {
    uint32_t a;
    asm("{ .reg .u64 t; cvta.to.shared.u64 t, %1; cvt.u32.u64 %0, t; }" : "=r"(a) : "l"(p));
    return a;
}

// ---------------- kernel 1: zero beta accumulators + halo rows ----------------
__global__ void prep_zero() {
    int tid = threadIdx.x;
    if (tid < B_SZ) g_beta_sum[tid] = 0.0f;
    for (int i = tid; i < B_SZ * C_IN; i += 256) {
        int b = i >> 8, c = i & 255;
        g_xb[((size_t)b * TP) * C_IN + c] = 0;
        g_xb[((size_t)b * TP + (TP - 1)) * C_IN + c] = 0;
    }
}

// ---------------- kernel 2: binarize + transpose x, accumulate |x| ----------------
// grid (250, 4, 8), block 256. Tile [64 cin][64 t] -> [64 t][64 cin] int8.
// smem layout: byte (t, ci) at t*64 + (ci ^ ((t>>4)<<4))  (16B-block XOR swizzle)
__global__ void prep_x(const float* __restrict__ x) {
    __shared__ signed char st[4096];
    __shared__ float red[8];
    int b = blockIdx.z, c0 = blockIdx.y * 64, t0 = blockIdx.x * 64;
    int tid = threadIdx.x;
    int ci = tid >> 2, tj0 = (tid & 3) * 16;
    int tq = tid & 3;                       // == t_local>>4 for all 16 elements
    int cisw = ci ^ (tq << 4);

    const float4* xp = (const float4*)(x + ((size_t)(b * C_IN + c0 + ci)) * T_SZ + t0 + tj0);
    float acc = 0.0f;
#pragma unroll
    for (int v = 0; v < 4; v++) {
        float4 f = xp[v];
        float vals[4] = {f.x, f.y, f.z, f.w};
#pragma unroll
        for (int e = 0; e < 4; e++) {
            float val = vals[e];
            acc += fabsf(val);
            st[(tj0 + 4 * v + e) * 64 + cisw] = (val >= 0.0f) ? (signed char)1 : (signed char)-1;
        }
    }
#pragma unroll
    for (int off = 16; off > 0; off >>= 1)
        acc += __shfl_xor_sync(0xFFFFFFFFu, acc, off);
    if ((tid & 31) == 0) red[tid >> 5] = acc;
    __syncthreads();
    if (tid == 0) {
        float s = 0.0f;
#pragma unroll
        for (int i = 0; i < 8; i++) s += red[i];
        atomicAdd(&g_beta_sum[b], s);
    }
    // read row tr, 16 cin chunk part*16 (aligned uint4, swizzle-consistent)
    int tr = tid >> 2, part = tid & 3;
    uint4 v = *(const uint4*)(st + tr * 64 + ((part * 16) ^ (((tr >> 4) & 3) << 4)));
    *(uint4*)(g_xb + ((size_t)b * TP + (t0 + tr + 1)) * C_IN + c0 + part * 16) = v;
}

// ---------------- kernel 3: alpha + packed sign weights ----------------
__global__ void prep_w(const float* __restrict__ w) {
    int co = blockIdx.x * 256 + threadIdx.x;
    if (co >= C_OUT) return;
    const float* wr = w + (size_t)co * 768;
    float s = 0.0f;
#pragma unroll 4
    for (int j = 0; j < 768; j++) s += fabsf(wr[j]);
    g_alpha[co] = s * (1.0f / 768.0f);
    signed char* wa = g_wA + (size_t)co * 768;
    for (int cin = 0; cin < C_IN; cin++) {
#pragma unroll
        for (int tap = 0; tap < 3; tap++)
            wa[tap * 256 + cin] = (wr[cin * 3 + tap] >= 0.0f) ? (signed char)1 : (signed char)-1;
    }
}

// ---------------- GEMM: persistent mma.sync int8 ----------------
// B smem: row r (= token t0-1+r), 256B; byte (r, col) at r*256 + (col ^ ((r&7)<<4))
__device__ __forceinline__ void issue_tile(uint32_t slot, int b, int t0, int tid) {
    const signed char* src = g_xb + ((size_t)b * TP + t0) * C_IN;
#pragma unroll
    for (int k = 0; k < 5; k++) {
        int idx = tid + k * 256;
        if (idx < NCHUNK) {
            int r = idx >> 4, c = idx & 15;
            uint32_t dst = slot + r * 256 + ((c * 16) ^ ((r & 7) << 4));
            asm volatile("cp.async.cg.shared.global [%0], [%1], 16;"
                         :: "r"(dst), "l"(src + r * 256 + c * 16) : "memory");
        }
    }
}

#define MMA_S8(D, A, B0, B1)                                                        \
    asm volatile("mma.sync.aligned.m16n8k32.row.col.s32.s8.s8.s32 "                  \
                 "{%0,%1,%2,%3}, {%4,%5,%6,%7}, {%8,%9}, {%0,%1,%2,%3};"             \
                 : "+r"(D[0]), "+r"(D[1]), "+r"(D[2]), "+r"(D[3])                    \
                 : "r"(A[0]), "r"(A[1]), "r"(A[2]), "r"(A[3]), "r"(B0), "r"(B1))

__global__ void __launch_bounds__(256, 1)
gemm_kernel(float* __restrict__ out) {
    __shared__ __align__(256) signed char smemB[2][STAGE_B];
    uint32_t sb0 = smem_u32(&smemB[0][0]);
    int tid = threadIdx.x, wid = tid >> 5, lane = tid & 31;
    int gID = lane >> 2, tig = lane & 3;
    int m = blockIdx.x & 3, q = blockIdx.x >> 2;
    int ntiles = (N_TILES_TOTAL - q + QMAX - 1) / QMAX;

    // ---- A fragments resident in registers (96 regs) ----
    int co0 = m * 128 + wid * 16 + gID;
    const uint32_t* wa0 = (const uint32_t*)(g_wA + (size_t)co0 * 768);
    const uint32_t* wa1 = (const uint32_t*)(g_wA + (size_t)(co0 + 8) * 768);
    uint32_t afr[24][4];
#pragma unroll
    for (int kc = 0; kc < 24; kc++) {
        afr[kc][0] = wa0[kc * 8 + tig];       // rows gID,   k = kc*32 + tig*4 .. +3
        afr[kc][1] = wa1[kc * 8 + tig];       // rows gID+8
        afr[kc][2] = wa0[kc * 8 + 4 + tig];   // k + 16
        afr[kc][3] = wa1[kc * 8 + 4 + tig];
    }
    float alpha0 = g_alpha[co0], alpha1 = g_alpha[co0 + 8];

    // ldmatrix per-thread address components: lane -> (matrix m_ld, row r_ld)
    int r_ld = lane & 7, m_ld = lane >> 3;
    int coffb = (m_ld >> 1) * 32 + (m_ld & 1) * 16;  // cin offset within 64-pair

    // ---- prologue: stage tiles 0,1 ----
    for (int s = 0; s < 2; s++) {
        if (s < ntiles) {
            int n = q + QMAX * s;
            int b = n / TILES_T, tl = n - b * TILES_T;
            issue_tile(sb0 + s * STAGE_B, b, tl * 64, tid);
        }
        asm volatile("cp.async.commit_group;" ::: "memory");
    }

    for (int j = 0; j < ntiles; j++) {
        int n = q + QMAX * j;
        int b = n / TILES_T, tl = n - b * TILES_T;
        asm volatile("cp.async.wait_group 1;" ::: "memory");
        __syncthreads();
        uint32_t stage = sb0 + (uint32_t)(j & 1) * STAGE_B;

        uint32_t base[3], swz[3];
#pragma unroll
        for (int tap = 0; tap < 3; tap++) {
            base[tap] = stage + (uint32_t)(r_ld + tap) * 256;
            swz[tap] = (uint32_t)((r_ld + tap) & 7) << 4;
        }

        int32_t acc[8][4];
#pragma unroll
        for (int nb = 0; nb < 8; nb++) {
            acc[nb][0] = 0; acc[nb][1] = 0; acc[nb][2] = 0; acc[nb][3] = 0;
        }

#pragma unroll
        for (int nb = 0; nb < 8; nb++) {
#pragma unroll
            for (int tap = 0; tap < 3; tap++) {
#pragma unroll
                for (int p = 0; p < 4; p++) {
                    uint32_t addr = base[tap] + (uint32_t)nb * 2048 +
                                    (((uint32_t)(p * 64 + coffb)) ^ swz[tap]);
                    uint32_t b0, b1, b2, b3;
                    asm volatile("ldmatrix.sync.aligned.m8n8.x4.shared.b16 {%0,%1,%2,%3}, [%4];"
                                 : "=r"(b0), "=r"(b1), "=r"(b2), "=r"(b3) : "r"(addr));
                    int kc = tap * 8 + p * 2;
                    MMA_S8(acc[nb], afr[kc], b0, b1);
                    MMA_S8(acc[nb], afr[kc + 1], b2, b3);
                }
            }
        }

        // ---- epilogue: scale + coalesced stores ----
        float sc = g_beta_sum[b] * INV_CNT;
        float s0 = alpha0 * sc, s1 = alpha1 * sc;
        float* ob = out + ((size_t)(b * C_OUT + co0)) * T_SZ + tl * 64 + tig * 2;
        float* ob8 = ob + (size_t)8 * T_SZ;
#pragma unroll
        for (int nb = 0; nb < 8; nb++) {
            float2 v0 = make_float2((float)acc[nb][0] * s0, (float)acc[nb][1] * s0);
            float2 v1 = make_float2((float)acc[nb][2] * s1, (float)acc[nb][3] * s1);
            *(float2*)(ob + nb * 8) = v0;
            *(float2*)(ob8 + nb * 8) = v1;
        }

        __syncthreads();   // slot fully consumed
        if (j + 2 < ntiles) {
            int n2 = q + QMAX * (j + 2);
            int b2 = n2 / TILES_T, tl2 = n2 - b2 * TILES_T;
            issue_tile(sb0 + (uint32_t)(j & 1) * STAGE_B, b2, tl2 * 64, tid);
        }
        asm volatile("cp.async.commit_group;" ::: "memory");
    }
}

// ---------------- host launcher ----------------
extern "C" void kernel_launch(void* const* d_in, const int* in_sizes, int n_in,
                              void* d_out, int out_size) {
    const float* x = (const float*)d_in[0];
    const float* w = (const float*)d_in[1];
    float* out = (float*)d_out;

    prep_zero<<<1, 256>>>();
    prep_x<<<dim3(TILES_T, 4, B_SZ), 256>>>(x);
    prep_w<<<2, 256>>>(w);
    gemm_kernel<<<148, 256>>>(out);
}